// round 9
// baseline (speedup 1.0000x reference)
#include <cuda_runtime.h>
#include <cuda_bf16.h>
#include <mma.h>

using namespace nvcuda;

#define DIMC  512
#define HIDN  1024
#define NB    16
#define NH    64
#define NW    64
#define NROWS (NB*NH*NW)   /* 65536 */

// ---------------- device scratch (static: no allocation in kernel_launch) ---
__device__ __align__(16) float          g_h[(size_t)NROWS*DIMC];      // LN1 out
__device__ __align__(16) float          g_x1[(size_t)NROWS*DIMC];     // residual 1
__device__ __align__(16) __nv_bfloat16  g_xn[(size_t)NROWS*DIMC];     // l2norm(LN2(x1))
__device__ __align__(16) __nv_bfloat16  g_hidden[(size_t)NROWS*HIDN]; // gelu(sim*si)
__device__ __align__(16) __nv_bfloat16  g_win[DIMC*HIDN];             // col-normalized proto_in
__device__ __align__(16) __nv_bfloat16  g_wout[HIDN*DIMC];            // col-normalized proto_out
__device__ __align__(16) float          g_gp[NB*DIMC];                // spatial sum per (b,c)
__device__ float                        g_rowsq[NROWS];               // sum hidden^2 per row

// ---------------- helpers ---------------------------------------------------
__device__ __forceinline__ float2 block_reduce2(float a, float b) {
    __shared__ float sa[33], sb[33];
    const unsigned FM = 0xffffffffu;
#pragma unroll
    for (int o = 16; o; o >>= 1) { a += __shfl_xor_sync(FM, a, o); b += __shfl_xor_sync(FM, b, o); }
    int w = threadIdx.x >> 5, l = threadIdx.x & 31;
    int nw = blockDim.x >> 5;
    __syncthreads();                        // protect reuse across calls
    if (l == 0) { sa[w] = a; sb[w] = b; }
    __syncthreads();
    if (w == 0) {
        a = (l < nw) ? sa[l] : 0.f;
        b = (l < nw) ? sb[l] : 0.f;
#pragma unroll
        for (int o = 4; o; o >>= 1) { a += __shfl_xor_sync(FM, a, o); b += __shfl_xor_sync(FM, b, o); }
        if (l == 0) { sa[32] = a; sb[32] = b; }
    }
    __syncthreads();
    return make_float2(sa[32], sb[32]);
}

__device__ __forceinline__ float gelu_f(float x) {
    return 0.5f * x * (1.0f + erff(x * 0.70710678118654752f));
}

// ---------------- K0: zero accumulators -------------------------------------
__global__ void k_zero() {
    int i = blockIdx.x * blockDim.x + threadIdx.x;
    if (i < NROWS)    g_rowsq[i] = 0.f;
    if (i < NB*DIMC)  g_gp[i]    = 0.f;
}

// ---------------- K1: LayerNorm1 + global-pool accumulation -----------------
// one CTA per (b, h): 64 rows of 512 channels; thread handles channels tid, tid+256
__global__ __launch_bounds__(256) void k_ln1(const float* __restrict__ x,
                                             const float* __restrict__ w,
                                             const float* __restrict__ b) {
    int bh = blockIdx.x;                 // 0..1023
    int batch = bh / NH;
    int t = threadIdx.x;
    int c0 = t, c1 = t + 256;
    float w0 = w[c0], w1 = w[c1], b0 = b[c0], b1 = b[c1];
    float acc0 = 0.f, acc1 = 0.f;
    size_t base = (size_t)bh * NW * DIMC;
    for (int j = 0; j < NW; j++) {
        size_t o = base + (size_t)j * DIMC;
        float v0 = x[o + c0], v1 = x[o + c1];
        float2 r = block_reduce2(v0 + v1, v0 * v0 + v1 * v1);
        float mean = r.x * (1.f / DIMC);
        float var  = r.y * (1.f / DIMC) - mean * mean;
        float inv  = rsqrtf(var + 1e-5f);
        float h0 = (v0 - mean) * inv * w0 + b0;
        float h1 = (v1 - mean) * inv * w1 + b1;
        g_h[o + c0] = h0; g_h[o + c1] = h1;
        acc0 += h0; acc1 += h1;
    }
    atomicAdd(&g_gp[batch * DIMC + c0], acc0);
    atomicAdd(&g_gp[batch * DIMC + c1], acc1);
}

// ---------------- K2: spatial + residual1 + LayerNorm2 + row L2 norm --------
// one CTA per row; 128 threads * 4 channels (float4)
__global__ __launch_bounds__(128) void k_spatial(const float* __restrict__ x,
                                                 const float* __restrict__ alpha,
                                                 const float* __restrict__ w2,
                                                 const float* __restrict__ b2,
                                                 const float* __restrict__ gamma) {
    int r = blockIdx.x;
    int batch = r >> 12;
    int rem = r & 4095;
    int i = rem >> 6, j = rem & 63;
    int c = threadIdx.x * 4;
    size_t ro = (size_t)r * DIMC;

    float4 z = make_float4(0.f, 0.f, 0.f, 0.f);
    float4 h  = *(const float4*)&g_h[ro + c];
    float4 up = (i > 0)      ? *(const float4*)&g_h[ro - (size_t)NW * DIMC + c] : z;
    float4 dn = (i < NH - 1) ? *(const float4*)&g_h[ro + (size_t)NW * DIMC + c] : z;
    float4 lf = (j > 0)      ? *(const float4*)&g_h[ro - DIMC + c] : z;
    float4 rt = (j < NW - 1) ? *(const float4*)&g_h[ro + DIMC + c] : z;
    float4 al = *(const float4*)&alpha[c];
    float4 gm = *(const float4*)&gamma[c];
    float4 gp = *(const float4*)&g_gp[batch * DIMC + c];
    float4 xv = *(const float4*)&x[ro + c];
    const float inv_hw = 1.f / 4096.f;

    float e0 = fabsf(h.x-up.x)+fabsf(h.x-dn.x)+fabsf(h.x-lf.x)+fabsf(h.x-rt.x);
    float e1 = fabsf(h.y-up.y)+fabsf(h.y-dn.y)+fabsf(h.y-lf.y)+fabsf(h.y-rt.y);
    float e2 = fabsf(h.z-up.z)+fabsf(h.z-dn.z)+fabsf(h.z-lf.z)+fabsf(h.z-rt.z);
    float e3 = fabsf(h.w-up.w)+fabsf(h.w-dn.w)+fabsf(h.w-lf.w)+fabsf(h.w-rt.w);

    float x10 = xv.x + gm.x * (e0 * al.x + gp.x * inv_hw * (1.f - al.x));
    float x11 = xv.y + gm.y * (e1 * al.y + gp.y * inv_hw * (1.f - al.y));
    float x12 = xv.z + gm.z * (e2 * al.z + gp.z * inv_hw * (1.f - al.z));
    float x13 = xv.w + gm.w * (e3 * al.w + gp.w * inv_hw * (1.f - al.w));

    *(float4*)&g_x1[ro + c] = make_float4(x10, x11, x12, x13);

    float2 rr = block_reduce2(x10 + x11 + x12 + x13,
                              x10*x10 + x11*x11 + x12*x12 + x13*x13);
    float mean = rr.x * (1.f / DIMC);
    float var  = rr.y * (1.f / DIMC) - mean * mean;
    float inv  = rsqrtf(var + 1e-5f);

    float4 wv = *(const float4*)&w2[c];
    float4 bv = *(const float4*)&b2[c];
    float h20 = (x10 - mean) * inv * wv.x + bv.x;
    float h21 = (x11 - mean) * inv * wv.y + bv.y;
    float h22 = (x12 - mean) * inv * wv.z + bv.z;
    float h23 = (x13 - mean) * inv * wv.w + bv.w;

    float2 r2 = block_reduce2(h20*h20 + h21*h21 + h22*h22 + h23*h23, 0.f);
    float invn = 1.f / fmaxf(sqrtf(r2.x), 1e-12f);

    *(__nv_bfloat162*)&g_xn[ro + c]     = __floats2bfloat162_rn(h20 * invn, h21 * invn);
    *(__nv_bfloat162*)&g_xn[ro + c + 2] = __floats2bfloat162_rn(h22 * invn, h23 * invn);
}

// ---------------- K3a/K3b: column-l2-normalized prototypes ------------------
__global__ __launch_bounds__(128) void k_wnorm_in(const float* __restrict__ p) {
    int col = blockIdx.x;     // 0..HIDN-1, norm over 512 rows
    int t = threadIdx.x;
    float v[4]; float sq = 0.f;
#pragma unroll
    for (int q = 0; q < 4; q++) {
        v[q] = p[(size_t)(t + q * 128) * HIDN + col];
        sq += v[q] * v[q];
    }
    float2 rr = block_reduce2(sq, 0.f);
    float invn = 1.f / fmaxf(sqrtf(rr.x), 1e-12f);
#pragma unroll
    for (int q = 0; q < 4; q++)
        g_win[(size_t)(t + q * 128) * HIDN + col] = __float2bfloat16(v[q] * invn);
}

__global__ __launch_bounds__(128) void k_wnorm_out(const float* __restrict__ p) {
    int col = blockIdx.x;     // 0..DIMC-1, norm over 1024 rows
    int t = threadIdx.x;
    float v[8]; float sq = 0.f;
#pragma unroll
    for (int q = 0; q < 8; q++) {
        v[q] = p[(size_t)(t + q * 128) * DIMC + col];
        sq += v[q] * v[q];
    }
    float2 rr = block_reduce2(sq, 0.f);
    float invn = 1.f / fmaxf(sqrtf(rr.x), 1e-12f);
#pragma unroll
    for (int q = 0; q < 8; q++)
        g_wout[(size_t)(t + q * 128) * DIMC + col] = __float2bfloat16(v[q] * invn);
}

// ---------------- K4/K5: bf16 wmma GEMMs with fused epilogues ----------------
// MODE 1: hidden = gelu(xn @ win * scale_in); rowsq += sum(hidden^2) per row
// MODE 2: out = x1 + gamma * (hidden @ wout) * scale_out / max(||hidden||,eps)
template <int KTOT, int NTOT, int MODE>
__global__ __launch_bounds__(256) void k_gemm(const float* __restrict__ sc,
                                              const float* __restrict__ gamma,
                                              float* __restrict__ out) {
    constexpr int BM = 128, BN = 64, BK = 32;
    __shared__ __align__(16) __nv_bfloat16 As[BM * BK];
    __shared__ __align__(16) __nv_bfloat16 Bs[BK * BN];
    __shared__ float Csm[BM * BN];

    const __nv_bfloat16* __restrict__ A = (MODE == 1) ? g_xn  : g_hidden;
    const __nv_bfloat16* __restrict__ B = (MODE == 1) ? g_win : g_wout;

    int tid = threadIdx.x;
    int m0 = blockIdx.y * BM, n0 = blockIdx.x * BN;
    int warp = tid >> 5;
    int wm = warp & 3, wn = warp >> 2;     // 4 x 2 warp grid, each 32x32

    wmma::fragment<wmma::accumulator, 16, 16, 16, float> c[2][2];
#pragma unroll
    for (int i = 0; i < 2; i++)
#pragma unroll
        for (int j = 0; j < 2; j++) wmma::fill_fragment(c[i][j], 0.f);

    for (int k0 = 0; k0 < KTOT; k0 += BK) {
#pragma unroll
        for (int ch = tid; ch < 512; ch += 256) {
            int row = ch >> 2, cc = ch & 3;
            *(uint4*)&As[row * BK + cc * 8] =
                *(const uint4*)&A[(size_t)(m0 + row) * KTOT + k0 + cc * 8];
        }
        {
            int row = tid >> 3, cc = tid & 7;
            *(uint4*)&Bs[row * BN + cc * 8] =
                *(const uint4*)&B[(size_t)(k0 + row) * NTOT + n0 + cc * 8];
        }
        __syncthreads();
#pragma unroll
        for (int ks = 0; ks < 2; ks++) {
            wmma::fragment<wmma::matrix_a, 16, 16, 16, __nv_bfloat16, wmma::row_major> af[2];
            wmma::fragment<wmma::matrix_b, 16, 16, 16, __nv_bfloat16, wmma::row_major> bf[2];
#pragma unroll
            for (int i = 0; i < 2; i++)
                wmma::load_matrix_sync(af[i], &As[(wm * 32 + i * 16) * BK + ks * 16], BK);
#pragma unroll
            for (int j = 0; j < 2; j++)
                wmma::load_matrix_sync(bf[j], &Bs[(ks * 16) * BN + wn * 32 + j * 16], BN);
#pragma unroll
            for (int i = 0; i < 2; i++)
#pragma unroll
                for (int j = 0; j < 2; j++)
                    wmma::mma_sync(c[i][j], af[i], bf[j], c[i][j]);
        }
        __syncthreads();
    }

#pragma unroll
    for (int i = 0; i < 2; i++)
#pragma unroll
        for (int j = 0; j < 2; j++)
            wmma::store_matrix_sync(&Csm[(wm * 32 + i * 16) * BN + wn * 32 + j * 16],
                                    c[i][j], BN, wmma::mem_row_major);
    __syncthreads();

    if (MODE == 1) {
        float si = sc[0];
#pragma unroll
        for (int e = 0; e < 16; e++) {
            int idx2 = e * 256 + tid;
            int row = idx2 >> 5, col2 = idx2 & 31;
            float g0 = gelu_f(Csm[row * BN + col2 * 2]     * si);
            float g1 = gelu_f(Csm[row * BN + col2 * 2 + 1] * si);
            *(__nv_bfloat162*)&g_hidden[(size_t)(m0 + row) * NTOT + n0 + col2 * 2] =
                __floats2bfloat162_rn(g0, g1);
            Csm[row * BN + col2 * 2]     = g0;     // keep fp32 for rowsq
            Csm[row * BN + col2 * 2 + 1] = g1;
        }
        __syncthreads();
        int row = tid >> 1, half = tid & 1;
        float s = 0.f;
#pragma unroll
        for (int t2 = 0; t2 < 32; t2++) {
            float g = Csm[row * BN + half * 32 + t2];
            s += g * g;
        }
        s += __shfl_xor_sync(0xffffffffu, s, 1);
        if (half == 0) atomicAdd(&g_rowsq[m0 + row], s);
    } else {
        float so = sc[0];
#pragma unroll
        for (int e = 0; e < 32; e++) {
            int idx = e * 256 + tid;
            int row = idx >> 6, col = idx & 63;
            int grow = m0 + row, gcol = n0 + col;
            float f = so / fmaxf(sqrtf(g_rowsq[grow]), 1e-12f);
            size_t go = (size_t)grow * DIMC + gcol;
            out[go] = g_x1[go] + gamma[gcol] * Csm[row * BN + col] * f;
        }
    }
}

// ---------------- launch -----------------------------------------------------
extern "C" void kernel_launch(void* const* d_in, const int* in_sizes, int n_in,
                              void* d_out, int out_size) {
    const float* x     = (const float*)d_in[0];
    const float* n1w   = (const float*)d_in[1];
    const float* n1b   = (const float*)d_in[2];
    const float* alpha = (const float*)d_in[3];
    const float* n2w   = (const float*)d_in[4];
    const float* n2b   = (const float*)d_in[5];
    const float* pin   = (const float*)d_in[6];
    const float* pout  = (const float*)d_in[7];
    const float* s_in  = (const float*)d_in[8];
    const float* s_out = (const float*)d_in[9];
    const float* gamma = (const float*)d_in[10];
    float* out = (float*)d_out;

    k_zero<<<(NROWS + 255) / 256, 256>>>();
    k_ln1<<<NB * NH, 256>>>(x, n1w, n1b);
    k_wnorm_in<<<HIDN, 128>>>(pin);
    k_wnorm_out<<<DIMC, 128>>>(pout);
    k_spatial<<<NROWS, 128>>>(x, alpha, n2w, n2b, gamma);

    dim3 g1(HIDN / 64, NROWS / 128);
    k_gemm<DIMC, HIDN, 1><<<g1, 256>>>(s_in, nullptr, nullptr);

    dim3 g2(DIMC / 64, NROWS / 128);
    k_gemm<HIDN, DIMC, 2><<<g2, 256>>>(s_out, gamma, out);
}